// round 2
// baseline (speedup 1.0000x reference)
#include <cuda_runtime.h>

#define N_DIST 1024
#define DIM    128
#define HID    256
#define MAXN   500000

// Scratch (no allocations allowed) — all fully rewritten every launch.
__device__ int   g_counts[N_DIST];
__device__ int   g_offsets[N_DIST + 1];
__device__ int   g_cursor[N_DIST];
__device__ int   g_order[MAXN];
__device__ float g_head[N_DIST * DIM];

// ---------------------------------------------------------------- reset
__global__ void k_reset() {
    g_counts[threadIdx.x] = 0;
}

// ---------------------------------------------------------------- histogram
__global__ void k_hist(const int* __restrict__ zone, int n) {
    __shared__ int sh[N_DIST];
    for (int i = threadIdx.x; i < N_DIST; i += blockDim.x) sh[i] = 0;
    __syncthreads();
    int stride = gridDim.x * blockDim.x;
    for (int i = blockIdx.x * blockDim.x + threadIdx.x; i < n; i += stride)
        atomicAdd(&sh[zone[i]], 1);
    __syncthreads();
    for (int i = threadIdx.x; i < N_DIST; i += blockDim.x) {
        int c = sh[i];
        if (c) atomicAdd(&g_counts[i], c);
    }
}

// ---------------------------------------------------------------- scan (1024, one block)
__global__ void k_scan() {
    __shared__ int s[N_DIST];
    int t = threadIdx.x;
    int cnt = g_counts[t];
    s[t] = cnt;
    __syncthreads();
    for (int off = 1; off < N_DIST; off <<= 1) {
        int add = (t >= off) ? s[t - off] : 0;
        __syncthreads();
        s[t] += add;
        __syncthreads();
    }
    g_offsets[t + 1] = s[t];
    if (t == 0) g_offsets[0] = 0;
    g_cursor[t] = s[t] - cnt;   // exclusive offset
}

// ---------------------------------------------------------------- scatter indices
__global__ void k_scatter(const int* __restrict__ zone, int n) {
    int stride = gridDim.x * blockDim.x;
    for (int i = blockIdx.x * blockDim.x + threadIdx.x; i < n; i += stride) {
        int z = zone[i];
        int p = atomicAdd(&g_cursor[z], 1);
        g_order[p] = i;
    }
}

// ---------------------------------------------------------------- gather-sum + ReLU
// One block per district, 128 threads; each thread owns one column.
__global__ void __launch_bounds__(DIM) k_gather(const float* __restrict__ x) {
    int d = blockIdx.x, t = threadIdx.x;
    int s = g_offsets[d], e = g_offsets[d + 1];
    float a0 = 0.f, a1 = 0.f, a2 = 0.f, a3 = 0.f;
    int j = s;
    for (; j + 8 <= e; j += 8) {
        int i0 = g_order[j + 0], i1 = g_order[j + 1];
        int i2 = g_order[j + 2], i3 = g_order[j + 3];
        int i4 = g_order[j + 4], i5 = g_order[j + 5];
        int i6 = g_order[j + 6], i7 = g_order[j + 7];
        a0 += x[(size_t)i0 * DIM + t];
        a1 += x[(size_t)i1 * DIM + t];
        a2 += x[(size_t)i2 * DIM + t];
        a3 += x[(size_t)i3 * DIM + t];
        a0 += x[(size_t)i4 * DIM + t];
        a1 += x[(size_t)i5 * DIM + t];
        a2 += x[(size_t)i6 * DIM + t];
        a3 += x[(size_t)i7 * DIM + t];
    }
    for (; j < e; ++j)
        a0 += x[(size_t)g_order[j] * DIM + t];
    float acc = (a0 + a1) + (a2 + a3);
    g_head[d * DIM + t] = fmaxf(acc, 0.f);   // pre-ReLU'd head
}

// ---------------------------------------------------------------- MLP
// 128 blocks x 256 threads, 8 districts per block.
// Phase A: h1 = relu(head @ w1 + b1)  (thread t = hidden column t)
// Phase B: out = h1 @ w2 + b2         (thread t = (row-group t>>7, out column t&127))
__global__ void __launch_bounds__(256) k_mlp(
    const float* __restrict__ w1, const float* __restrict__ b1,
    const float* __restrict__ w2, const float* __restrict__ b2,
    float* __restrict__ out)
{
    __shared__ float sh_head[8][DIM];
    __shared__ float sh_h1[8][HID];
    int t = threadIdx.x;
    int base = blockIdx.x * 8;

    for (int idx = t; idx < 8 * DIM; idx += 256)
        sh_head[idx >> 7][idx & 127] = g_head[base * DIM + idx];
    __syncthreads();

    // Phase A
    {
        int col = t;             // 0..255
        float acc[8];
        float bb = b1[col];
        #pragma unroll
        for (int r = 0; r < 8; r++) acc[r] = bb;
        #pragma unroll 4
        for (int k = 0; k < DIM; k++) {
            float w = w1[k * HID + col];
            #pragma unroll
            for (int r = 0; r < 8; r++) acc[r] += sh_head[r][k] * w;
        }
        #pragma unroll
        for (int r = 0; r < 8; r++) sh_h1[r][col] = fmaxf(acc[r], 0.f);
    }
    __syncthreads();

    // Phase B
    {
        int col = t & 127;
        int r0  = (t >> 7) * 4;  // rows r0..r0+3
        float acc[4];
        float bb = b2[col];
        #pragma unroll
        for (int r = 0; r < 4; r++) acc[r] = bb;
        #pragma unroll 4
        for (int k = 0; k < HID; k++) {
            float w = w2[k * DIM + col];
            #pragma unroll
            for (int r = 0; r < 4; r++) acc[r] += sh_h1[r0 + r][k] * w;
        }
        #pragma unroll
        for (int r = 0; r < 4; r++)
            out[(size_t)(base + r0 + r) * DIM + col] = acc[r];
    }
}

// ---------------------------------------------------------------- launch
extern "C" void kernel_launch(void* const* d_in, const int* in_sizes, int n_in,
                              void* d_out, int out_size) {
    const float* x    = (const float*)d_in[0];
    const int*   zone = (const int*)d_in[1];
    const float* w1   = (const float*)d_in[2];
    const float* b1   = (const float*)d_in[3];
    const float* w2   = (const float*)d_in[4];
    const float* b2   = (const float*)d_in[5];
    float*       out  = (float*)d_out;
    int n = in_sizes[1];   // number of nodes

    k_reset  <<<1, N_DIST>>>();
    k_hist   <<<148, 256>>>(zone, n);
    k_scan   <<<1, N_DIST>>>();
    k_scatter<<<256, 256>>>(zone, n);
    k_gather <<<N_DIST, DIM>>>(x);
    k_mlp    <<<N_DIST / 8, 256>>>(w1, b1, w2, b2, out);
}

// round 3
// speedup vs baseline: 1.1631x; 1.1631x over previous
#include <cuda_runtime.h>

#define N_DIST 1024
#define DIM    128
#define HID    256
#define MAXN   500000
#define NBLK   256

// Scratch (no allocations allowed) — fully rewritten every launch.
__device__ int   g_counts[NBLK * N_DIST];   // per-block histograms [b][d]
__device__ int   g_bcursor[NBLK * N_DIST];  // per-block exclusive prefix within district
__device__ int   g_total[N_DIST];
__device__ int   g_offsets[N_DIST + 1];
__device__ int   g_order[MAXN];
__device__ float g_head[N_DIST * DIM];

// ---------------------------------------------------------------- A: per-block histogram
__global__ void __launch_bounds__(256) k_hist(const int* __restrict__ zone, int n, int chunk) {
    __shared__ int sh[N_DIST];
    int b = blockIdx.x, t = threadIdx.x;
    for (int i = t; i < N_DIST; i += 256) sh[i] = 0;
    __syncthreads();
    int s = b * chunk, e = min(n, s + chunk);
    for (int i = s + t; i < e; i += 256)
        atomicAdd(&sh[zone[i]], 1);
    __syncthreads();
    for (int i = t; i < N_DIST; i += 256)
        g_counts[b * N_DIST + i] = sh[i];
}

// ---------------------------------------------------------------- B: scan over blocks per district
__global__ void __launch_bounds__(NBLK) k_scan_blocks() {
    __shared__ int s[NBLK];
    int d = blockIdx.x, t = threadIdx.x;
    int c = g_counts[t * N_DIST + d];
    s[t] = c;
    __syncthreads();
    for (int off = 1; off < NBLK; off <<= 1) {
        int add = (t >= off) ? s[t - off] : 0;
        __syncthreads();
        s[t] += add;
        __syncthreads();
    }
    g_bcursor[t * N_DIST + d] = s[t] - c;   // exclusive within district
    if (t == NBLK - 1) g_total[d] = s[t];
}

// ---------------------------------------------------------------- C: scan districts
__global__ void __launch_bounds__(N_DIST) k_scan() {
    __shared__ int s[N_DIST];
    int t = threadIdx.x;
    int cnt = g_total[t];
    s[t] = cnt;
    __syncthreads();
    for (int off = 1; off < N_DIST; off <<= 1) {
        int add = (t >= off) ? s[t - off] : 0;
        __syncthreads();
        s[t] += add;
        __syncthreads();
    }
    g_offsets[t + 1] = s[t];
    if (t == 0) g_offsets[0] = 0;
}

// ---------------------------------------------------------------- D: scatter (smem atomics only)
__global__ void __launch_bounds__(256) k_scatter(const int* __restrict__ zone, int n, int chunk) {
    __shared__ int cur[N_DIST];
    int b = blockIdx.x, t = threadIdx.x;
    for (int i = t; i < N_DIST; i += 256)
        cur[i] = g_offsets[i] + g_bcursor[b * N_DIST + i];
    __syncthreads();
    int s = b * chunk, e = min(n, s + chunk);
    for (int i = s + t; i < e; i += 256) {
        int z = zone[i];
        int p = atomicAdd(&cur[z], 1);
        g_order[p] = i;
    }
}

// ---------------------------------------------------------------- E: gather-sum + ReLU
// One block per district, 128 threads; each thread owns one column.
__global__ void __launch_bounds__(DIM) k_gather(const float* __restrict__ x) {
    int d = blockIdx.x, t = threadIdx.x;
    int s = g_offsets[d], e = g_offsets[d + 1];
    float a0 = 0.f, a1 = 0.f, a2 = 0.f, a3 = 0.f;
    int j = s;
    for (; j + 16 <= e; j += 16) {
        int idx[16];
        #pragma unroll
        for (int u = 0; u < 16; u++) idx[u] = g_order[j + u];
        #pragma unroll
        for (int u = 0; u < 16; u += 4) {
            a0 += x[(size_t)idx[u + 0] * DIM + t];
            a1 += x[(size_t)idx[u + 1] * DIM + t];
            a2 += x[(size_t)idx[u + 2] * DIM + t];
            a3 += x[(size_t)idx[u + 3] * DIM + t];
        }
    }
    for (; j < e; ++j)
        a0 += x[(size_t)g_order[j] * DIM + t];
    float acc = (a0 + a1) + (a2 + a3);
    g_head[d * DIM + t] = fmaxf(acc, 0.f);   // pre-ReLU'd head
}

// ---------------------------------------------------------------- F: MLP
// 128 blocks x 256 threads, 8 districts per block.
__global__ void __launch_bounds__(256) k_mlp(
    const float* __restrict__ w1, const float* __restrict__ b1,
    const float* __restrict__ w2, const float* __restrict__ b2,
    float* __restrict__ out)
{
    __shared__ float sh_head[8][DIM];
    __shared__ float sh_h1[8][HID];
    int t = threadIdx.x;
    int base = blockIdx.x * 8;

    for (int idx = t; idx < 8 * DIM; idx += 256)
        sh_head[idx >> 7][idx & 127] = g_head[base * DIM + idx];
    __syncthreads();

    // Phase A: h1 = relu(head @ w1 + b1), thread t = hidden column
    {
        int col = t;
        float acc[8];
        float bb = b1[col];
        #pragma unroll
        for (int r = 0; r < 8; r++) acc[r] = bb;
        #pragma unroll 4
        for (int k = 0; k < DIM; k++) {
            float w = w1[k * HID + col];
            #pragma unroll
            for (int r = 0; r < 8; r++) acc[r] += sh_head[r][k] * w;
        }
        #pragma unroll
        for (int r = 0; r < 8; r++) sh_h1[r][col] = fmaxf(acc[r], 0.f);
    }
    __syncthreads();

    // Phase B: out = h1 @ w2 + b2
    {
        int col = t & 127;
        int r0  = (t >> 7) * 4;
        float acc[4];
        float bb = b2[col];
        #pragma unroll
        for (int r = 0; r < 4; r++) acc[r] = bb;
        #pragma unroll 4
        for (int k = 0; k < HID; k++) {
            float w = w2[k * DIM + col];
            #pragma unroll
            for (int r = 0; r < 4; r++) acc[r] += sh_h1[r0 + r][k] * w;
        }
        #pragma unroll
        for (int r = 0; r < 4; r++)
            out[(size_t)(base + r0 + r) * DIM + col] = acc[r];
    }
}

// ---------------------------------------------------------------- launch
extern "C" void kernel_launch(void* const* d_in, const int* in_sizes, int n_in,
                              void* d_out, int out_size) {
    const float* x    = (const float*)d_in[0];
    const int*   zone = (const int*)d_in[1];
    const float* w1   = (const float*)d_in[2];
    const float* b1   = (const float*)d_in[3];
    const float* w2   = (const float*)d_in[4];
    const float* b2   = (const float*)d_in[5];
    float*       out  = (float*)d_out;
    int n = in_sizes[1];                 // number of nodes
    int chunk = (n + NBLK - 1) / NBLK;   // contiguous chunk per block

    k_hist       <<<NBLK, 256>>>(zone, n, chunk);
    k_scan_blocks<<<N_DIST, NBLK>>>();
    k_scan       <<<1, N_DIST>>>();
    k_scatter    <<<NBLK, 256>>>(zone, n, chunk);
    k_gather     <<<N_DIST, DIM>>>(x);
    k_mlp        <<<N_DIST / 8, 256>>>(w1, b1, w2, b2, out);
}

// round 5
// speedup vs baseline: 1.5109x; 1.2990x over previous
#include <cuda_runtime.h>

#define N_DIST 1024
#define DIM    128
#define HID    256
#define MAXN   500000
#define NBLK   256
#define GCHUNK 2048

// Scratch (no allocations allowed) — fully rewritten every launch.
__device__ int   g_counts[NBLK * N_DIST];   // per-block histograms [b][d]
__device__ int   g_bcursor[NBLK * N_DIST];  // per-block exclusive prefix within district
__device__ int   g_total[N_DIST];
__device__ int   g_offsets[N_DIST + 1];
__device__ int   g_order[MAXN];
__device__ float g_head[N_DIST * DIM];

// ---------------------------------------------------------------- A: per-block histogram
__global__ void __launch_bounds__(256) k_hist(const int* __restrict__ zone, int n, int chunk) {
    __shared__ int sh[N_DIST];
    int b = blockIdx.x, t = threadIdx.x;
    for (int i = t; i < N_DIST; i += 256) sh[i] = 0;
    __syncthreads();
    int s = b * chunk, e = min(n, s + chunk);
    for (int i = s + t; i < e; i += 256)
        atomicAdd(&sh[zone[i]], 1);
    __syncthreads();
    for (int i = t; i < N_DIST; i += 256)
        g_counts[b * N_DIST + i] = sh[i];
}

// ---------------------------------------------------------------- B: scan over blocks per district
__global__ void __launch_bounds__(NBLK) k_scan_blocks() {
    __shared__ int s[NBLK];
    int d = blockIdx.x, t = threadIdx.x;
    int c = g_counts[t * N_DIST + d];
    s[t] = c;
    __syncthreads();
    for (int off = 1; off < NBLK; off <<= 1) {
        int add = (t >= off) ? s[t - off] : 0;
        __syncthreads();
        s[t] += add;
        __syncthreads();
    }
    g_bcursor[t * N_DIST + d] = s[t] - c;   // exclusive within district
    if (t == NBLK - 1) g_total[d] = s[t];
}

// ---------------------------------------------------------------- C: scan districts
__global__ void __launch_bounds__(N_DIST) k_scan() {
    __shared__ int s[N_DIST];
    int t = threadIdx.x;
    int cnt = g_total[t];
    s[t] = cnt;
    __syncthreads();
    for (int off = 1; off < N_DIST; off <<= 1) {
        int add = (t >= off) ? s[t - off] : 0;
        __syncthreads();
        s[t] += add;
        __syncthreads();
    }
    g_offsets[t + 1] = s[t];
    if (t == 0) g_offsets[0] = 0;
}

// ---------------------------------------------------------------- D: scatter (smem atomics only)
__global__ void __launch_bounds__(256) k_scatter(const int* __restrict__ zone, int n, int chunk) {
    __shared__ int cur[N_DIST];
    int b = blockIdx.x, t = threadIdx.x;
    for (int i = t; i < N_DIST; i += 256)
        cur[i] = g_offsets[i] + g_bcursor[b * N_DIST + i];
    __syncthreads();
    int s = b * chunk, e = min(n, s + chunk);
    for (int i = s + t; i < e; i += 256) {
        int z = zone[i];
        int p = atomicAdd(&cur[z], 1);
        g_order[p] = i;
    }
}

// ---------------------------------------------------------------- E: gather-sum + ReLU (v2)
// One block per district, 256 threads = 8 warps. Each warp reads whole rows
// via float4 (LDG.128); indices staged in smem; cross-warp smem reduction.
__global__ void __launch_bounds__(256) k_gather(const float4* __restrict__ x4) {
    __shared__ int    sh_idx[GCHUNK];
    __shared__ float4 sh_part[8][32];
    int d = blockIdx.x, t = threadIdx.x;
    int w = t >> 5, lane = t & 31;
    int s = g_offsets[d], e = g_offsets[d + 1];
    int cnt = e - s;
    float4 acc = make_float4(0.f, 0.f, 0.f, 0.f);

    for (int base = 0; base < cnt; base += GCHUNK) {
        int m = min(GCHUNK, cnt - base);
        __syncthreads();                     // protect sh_idx reuse across chunks
        for (int i = t; i < m; i += 256)
            sh_idx[i] = g_order[s + base + i];
        __syncthreads();

        int r = w;
        for (; r + 32 <= m; r += 32) {       // 8 warps x 4-way unroll
            size_t p0 = (size_t)sh_idx[r]      * 32 + lane;
            size_t p1 = (size_t)sh_idx[r + 8]  * 32 + lane;
            size_t p2 = (size_t)sh_idx[r + 16] * 32 + lane;
            size_t p3 = (size_t)sh_idx[r + 24] * 32 + lane;
            float4 v0 = x4[p0];
            float4 v1 = x4[p1];
            float4 v2 = x4[p2];
            float4 v3 = x4[p3];
            acc.x += (v0.x + v1.x) + (v2.x + v3.x);
            acc.y += (v0.y + v1.y) + (v2.y + v3.y);
            acc.z += (v0.z + v1.z) + (v2.z + v3.z);
            acc.w += (v0.w + v1.w) + (v2.w + v3.w);
        }
        for (; r < m; r += 8) {
            float4 v = x4[(size_t)sh_idx[r] * 32 + lane];
            acc.x += v.x; acc.y += v.y; acc.z += v.z; acc.w += v.w;
        }
    }

    sh_part[w][lane] = acc;
    __syncthreads();
    if (w == 0) {
        float4 r = sh_part[0][lane];
        #pragma unroll
        for (int wi = 1; wi < 8; wi++) {
            float4 p = sh_part[wi][lane];
            r.x += p.x; r.y += p.y; r.z += p.z; r.w += p.w;
        }
        float4 o;
        o.x = fmaxf(r.x, 0.f); o.y = fmaxf(r.y, 0.f);
        o.z = fmaxf(r.z, 0.f); o.w = fmaxf(r.w, 0.f);
        ((float4*)g_head)[d * 32 + lane] = o;     // pre-ReLU'd head
    }
}

// ---------------------------------------------------------------- F: MLP
// 128 blocks x 256 threads, 8 districts per block.
__global__ void __launch_bounds__(256) k_mlp(
    const float* __restrict__ w1, const float* __restrict__ b1,
    const float* __restrict__ w2, const float* __restrict__ b2,
    float* __restrict__ out)
{
    __shared__ float sh_head[8][DIM];
    __shared__ float sh_h1[8][HID];
    int t = threadIdx.x;
    int base = blockIdx.x * 8;

    for (int idx = t; idx < 8 * DIM; idx += 256)
        sh_head[idx >> 7][idx & 127] = g_head[base * DIM + idx];
    __syncthreads();

    // Phase A: h1 = relu(head @ w1 + b1), thread t = hidden column
    {
        int col = t;
        float acc[8];
        float bb = b1[col];
        #pragma unroll
        for (int r = 0; r < 8; r++) acc[r] = bb;
        #pragma unroll 4
        for (int k = 0; k < DIM; k++) {
            float w = w1[k * HID + col];
            #pragma unroll
            for (int r = 0; r < 8; r++) acc[r] += sh_head[r][k] * w;
        }
        #pragma unroll
        for (int r = 0; r < 8; r++) sh_h1[r][col] = fmaxf(acc[r], 0.f);
    }
    __syncthreads();

    // Phase B: out = h1 @ w2 + b2
    {
        int col = t & 127;
        int r0  = (t >> 7) * 4;
        float acc[4];
        float bb = b2[col];
        #pragma unroll
        for (int r = 0; r < 4; r++) acc[r] = bb;
        #pragma unroll 4
        for (int k = 0; k < HID; k++) {
            float w = w2[k * DIM + col];
            #pragma unroll
            for (int r = 0; r < 4; r++) acc[r] += sh_h1[r0 + r][k] * w;
        }
        #pragma unroll
        for (int r = 0; r < 4; r++)
            out[(size_t)(base + r0 + r) * DIM + col] = acc[r];
    }
}

// ---------------------------------------------------------------- launch
extern "C" void kernel_launch(void* const* d_in, const int* in_sizes, int n_in,
                              void* d_out, int out_size) {
    const float* x    = (const float*)d_in[0];
    const int*   zone = (const int*)d_in[1];
    const float* w1   = (const float*)d_in[2];
    const float* b1   = (const float*)d_in[3];
    const float* w2   = (const float*)d_in[4];
    const float* b2   = (const float*)d_in[5];
    float*       out  = (float*)d_out;
    int n = in_sizes[1];                 // number of nodes
    int chunk = (n + NBLK - 1) / NBLK;   // contiguous chunk per block

    k_hist       <<<NBLK, 256>>>(zone, n, chunk);
    k_scan_blocks<<<N_DIST, NBLK>>>();
    k_scan       <<<1, N_DIST>>>();
    k_scatter    <<<NBLK, 256>>>(zone, n, chunk);
    k_gather     <<<N_DIST, 256>>>((const float4*)x);
    k_mlp        <<<N_DIST / 8, 256>>>(w1, b1, w2, b2, out);
}

// round 7
// speedup vs baseline: 1.8676x; 1.2361x over previous
#include <cuda_runtime.h>

#define N_DIST 1024
#define DIM    128
#define HID    256
#define MAXN   500000
#define NBLK   512
#define GCHUNK 2048

// Scratch (no allocations allowed) — fully rewritten every launch.
__device__ int   g_counts[NBLK * N_DIST];   // per-block histograms [b][d]
__device__ int   g_bcursor[NBLK * N_DIST];  // per-block exclusive prefix within district
__device__ int   g_total[N_DIST];
__device__ int   g_offsets[N_DIST + 1];
__device__ int   g_order[MAXN];
__device__ float g_head2[2][N_DIST * DIM];  // split-2 partial heads (pre-ReLU)

// ---------------------------------------------------------------- A: per-block histogram
__global__ void __launch_bounds__(256) k_hist(const int* __restrict__ zone, int n, int chunk) {
    __shared__ int sh[N_DIST];
    int b = blockIdx.x, t = threadIdx.x;
    for (int i = t; i < N_DIST; i += 256) sh[i] = 0;
    __syncthreads();
    int s = b * chunk, e = min(n, s + chunk);
    for (int i = s + t; i < e; i += 256)
        atomicAdd(&sh[zone[i]], 1);
    __syncthreads();
    for (int i = t; i < N_DIST; i += 256)
        g_counts[b * N_DIST + i] = sh[i];
}

// ---------------------------------------------------------------- B: scan over blocks per district
__global__ void __launch_bounds__(NBLK) k_scan_blocks() {
    __shared__ int s[NBLK];
    int d = blockIdx.x, t = threadIdx.x;
    int c = g_counts[t * N_DIST + d];
    s[t] = c;
    __syncthreads();
    for (int off = 1; off < NBLK; off <<= 1) {
        int add = (t >= off) ? s[t - off] : 0;
        __syncthreads();
        s[t] += add;
        __syncthreads();
    }
    g_bcursor[t * N_DIST + d] = s[t] - c;   // exclusive within district
    if (t == NBLK - 1) g_total[d] = s[t];
}

// ---------------------------------------------------------------- C: scan districts
__global__ void __launch_bounds__(N_DIST) k_scan() {
    __shared__ int s[N_DIST];
    int t = threadIdx.x;
    int cnt = g_total[t];
    s[t] = cnt;
    __syncthreads();
    for (int off = 1; off < N_DIST; off <<= 1) {
        int add = (t >= off) ? s[t - off] : 0;
        __syncthreads();
        s[t] += add;
        __syncthreads();
    }
    g_offsets[t + 1] = s[t];
    if (t == 0) g_offsets[0] = 0;
}

// ---------------------------------------------------------------- D: scatter (smem atomics only)
__global__ void __launch_bounds__(256) k_scatter(const int* __restrict__ zone, int n, int chunk) {
    __shared__ int cur[N_DIST];
    int b = blockIdx.x, t = threadIdx.x;
    for (int i = t; i < N_DIST; i += 256)
        cur[i] = g_offsets[i] + g_bcursor[b * N_DIST + i];
    __syncthreads();
    int s = b * chunk, e = min(n, s + chunk);
    for (int i = s + t; i < e; i += 256) {
        int z = zone[i];
        int p = atomicAdd(&cur[z], 1);
        g_order[p] = i;
    }
}

// ---------------------------------------------------------------- E: gather-sum (split-2)
// 2048 blocks: district d = blockIdx>>1, half h = blockIdx&1. 256 threads = 8 warps,
// each warp reads whole 512B rows via LDG.128, 8 rows in flight per iteration.
__global__ void __launch_bounds__(256) k_gather(const float4* __restrict__ x4) {
    __shared__ int    sh_idx[GCHUNK];
    __shared__ float4 sh_part[8][32];
    int d = blockIdx.x >> 1, h = blockIdx.x & 1;
    int t = threadIdx.x;
    int w = t >> 5, lane = t & 31;
    int s0 = g_offsets[d], e0 = g_offsets[d + 1];
    int cnt0 = e0 - s0;
    int half = (cnt0 + 1) >> 1;
    int s = s0 + (h ? half : 0);
    int e = h ? e0 : (s0 + half);
    int cnt = e - s;
    float4 acc = make_float4(0.f, 0.f, 0.f, 0.f);

    for (int base = 0; base < cnt; base += GCHUNK) {
        int m = min(GCHUNK, cnt - base);
        __syncthreads();                     // protect sh_idx reuse across chunks
        for (int i = t; i < m; i += 256)
            sh_idx[i] = g_order[s + base + i];
        __syncthreads();

        int r = w;
        for (; r + 64 <= m; r += 64) {       // 8 warps x 8-way unroll
            float4 v[8];
            #pragma unroll
            for (int u = 0; u < 8; u++) {
                size_t p = (size_t)sh_idx[r + u * 8] * 32 + lane;
                v[u] = __ldcs(&x4[p]);
            }
            #pragma unroll
            for (int u = 0; u < 8; u++) {
                acc.x += v[u].x; acc.y += v[u].y;
                acc.z += v[u].z; acc.w += v[u].w;
            }
        }
        for (; r < m; r += 8) {
            float4 v = __ldcs(&x4[(size_t)sh_idx[r] * 32 + lane]);
            acc.x += v.x; acc.y += v.y; acc.z += v.z; acc.w += v.w;
        }
    }

    sh_part[w][lane] = acc;
    __syncthreads();
    if (w == 0) {
        float4 r = sh_part[0][lane];
        #pragma unroll
        for (int wi = 1; wi < 8; wi++) {
            float4 p = sh_part[wi][lane];
            r.x += p.x; r.y += p.y; r.z += p.z; r.w += p.w;
        }
        ((float4*)g_head2[h])[d * 32 + lane] = r;   // partial, no ReLU yet
    }
}

// ---------------------------------------------------------------- F: MLP
// 128 blocks x 256 threads, 8 districts per block. Combines split-2 partials + ReLU.
__global__ void __launch_bounds__(256) k_mlp(
    const float* __restrict__ w1, const float* __restrict__ b1,
    const float* __restrict__ w2, const float* __restrict__ b2,
    float* __restrict__ out)
{
    __shared__ float sh_head[8][DIM];
    __shared__ float sh_h1[8][HID];
    int t = threadIdx.x;
    int base = blockIdx.x * 8;

    for (int idx = t; idx < 8 * DIM; idx += 256) {
        float p = g_head2[0][base * DIM + idx] + g_head2[1][base * DIM + idx];
        sh_head[idx >> 7][idx & 127] = fmaxf(p, 0.f);
    }
    __syncthreads();

    // Phase A: h1 = relu(head @ w1 + b1), thread t = hidden column
    {
        int col = t;
        float acc[8];
        float bb = b1[col];
        #pragma unroll
        for (int r = 0; r < 8; r++) acc[r] = bb;
        #pragma unroll 4
        for (int k = 0; k < DIM; k++) {
            float w = w1[k * HID + col];
            #pragma unroll
            for (int r = 0; r < 8; r++) acc[r] += sh_head[r][k] * w;
        }
        #pragma unroll
        for (int r = 0; r < 8; r++) sh_h1[r][col] = fmaxf(acc[r], 0.f);
    }
    __syncthreads();

    // Phase B: out = h1 @ w2 + b2
    {
        int col = t & 127;
        int r0  = (t >> 7) * 4;
        float acc[4];
        float bb = b2[col];
        #pragma unroll
        for (int r = 0; r < 4; r++) acc[r] = bb;
        #pragma unroll 4
        for (int k = 0; k < HID; k++) {
            float w = w2[k * DIM + col];
            #pragma unroll
            for (int r = 0; r < 4; r++) acc[r] += sh_h1[r0 + r][k] * w;
        }
        #pragma unroll
        for (int r = 0; r < 4; r++)
            out[(size_t)(base + r0 + r) * DIM + col] = acc[r];
    }
}

// ---------------------------------------------------------------- launch
extern "C" void kernel_launch(void* const* d_in, const int* in_sizes, int n_in,
                              void* d_out, int out_size) {
    const float* x    = (const float*)d_in[0];
    const int*   zone = (const int*)d_in[1];
    const float* w1   = (const float*)d_in[2];
    const float* b1   = (const float*)d_in[3];
    const float* w2   = (const float*)d_in[4];
    const float* b2   = (const float*)d_in[5];
    float*       out  = (float*)d_out;
    int n = in_sizes[1];                 // number of nodes
    int chunk = (n + NBLK - 1) / NBLK;   // contiguous chunk per block

    k_hist       <<<NBLK, 256>>>(zone, n, chunk);
    k_scan_blocks<<<N_DIST, NBLK>>>();
    k_scan       <<<1, N_DIST>>>();
    k_scatter    <<<NBLK, 256>>>(zone, n, chunk);
    k_gather     <<<N_DIST * 2, 256>>>((const float4*)x);
    k_mlp        <<<N_DIST / 8, 256>>>(w1, b1, w2, b2, out);
}